// round 1
// baseline (speedup 1.0000x reference)
#include <cuda_runtime.h>

// Precomputed Pauli coefficients n_q = (nx, ny, nz) of U_q^dag Z U_q, per qubit.
// Written by the 1-warp prep kernel from the shared weights.
__device__ __align__(16) float g_n[12];

__global__ void vqc_prep(const float* __restrict__ w) {
    int q = threadIdx.x;
    if (q < 4) {
        // weights layout (NL=1, 4, 3): [theta, phi, lambda] per qubit; phi drops out.
        float th = w[q * 3 + 0];
        float lm = w[q * 3 + 2];
        float st, ct, sl, cl;
        sincosf(th, &st, &ct);   // precise path: only 4 threads, accuracy for free
        sincosf(lm, &sl, &cl);
        g_n[q * 3 + 0] = -st * cl;  // nx
        g_n[q * 3 + 1] =  st * sl;  // ny
        g_n[q * 3 + 2] =  ct;       // nz
    }
}

__global__ __launch_bounds__(256) void vqc_main(const float4* __restrict__ enc,
                                                float4* __restrict__ out,
                                                int B) {
    int i = blockIdx.x * blockDim.x + threadIdx.x;
    if (i >= B) return;

    // enc_angles is (B, 4, 3) fp32 -> 12 contiguous floats = 3 aligned float4s.
    float4 e0 = enc[3 * i + 0];
    float4 e1 = enc[3 * i + 1];
    float4 e2 = enc[3 * i + 2];
    float t[12] = {e0.x, e0.y, e0.z, e0.w,
                   e1.x, e1.y, e1.z, e1.w,
                   e2.x, e2.y, e2.z, e2.w};

    // Per-qubit Bloch vector after RZ(t0) RY(t1) RZ(t2) applied to |+>.
    float x[4], y[4], z[4];
#pragma unroll
    for (int q = 0; q < 4; q++) {
        float s0, c0, s1, c1, s2, c2;
        __sincosf(t[3 * q + 0], &s0, &c0);
        __sincosf(t[3 * q + 1], &s1, &c1);
        __sincosf(t[3 * q + 2], &s2, &c2);
        float cc = c0 * c1;
        x[q] = cc * c2 - s0 * s2;
        y[q] = cc * s2 + s0 * c2;
        z[q] = -c0 * s1;
    }

    // Uniform loads of the precomputed observable coefficients (L1-resident).
    const float4* n4 = (const float4*)g_n;
    float4 n0 = n4[0];  // {nx0, ny0, nz0, nx1}
    float4 n1 = n4[1];  // {ny1, nz1, nx2, ny2}
    float4 n2 = n4[2];  // {nz2, nx3, ny3, nz3}

    // Shared subproducts of Bloch components.
    float z01   = z[0] * z[1];
    float z23   = z[2] * z[3];
    float z012  = z01 * z[2];
    float z123  = z[1] * z23;
    float z0123 = z01 * z23;
    float x01   = x[0] * x[1];

    // <Z_q> via CNOT-ring-conjugated Pauli strings on the product state.
    float4 o;
    o.x = n0.x * x01           + n0.y * (x[0] * y[1] * z23)        + n0.z * z123;
    o.y = n0.w * (x[1] * x[2]) + n1.x * (z[0] * y[1] * x[2])       + n1.y * z01;
    o.z = n1.z * (x[2] * x[3]) + n1.w * (z01 * y[2] * x[3])        + n2.x * z012;
    o.w = n2.y * (x01 * x[3])  - n2.z * (y[0] * y[1] * z[2] * y[3]) + n2.w * z0123;

    out[i] = o;
}

extern "C" void kernel_launch(void* const* d_in, const int* in_sizes, int n_in,
                              void* d_out, int out_size) {
    // Identify inputs defensively: enc_angles is the big one (B*12), weights is 12.
    int ei = 0, wi = 1;
    if (n_in >= 2 && in_sizes[0] < in_sizes[1]) { ei = 1; wi = 0; }
    const float* enc = (const float*)d_in[ei];
    const float* w   = (const float*)d_in[wi];
    int B = in_sizes[ei] / 12;

    vqc_prep<<<1, 32>>>(w);

    const int threads = 256;
    int blocks = (B + threads - 1) / threads;
    vqc_main<<<blocks, threads>>>((const float4*)enc, (float4*)d_out, B);
}